// round 3
// baseline (speedup 1.0000x reference)
#include <cuda_runtime.h>
#include <cuda_bf16.h>
#include <math.h>
#include <float.h>

// Problem constants
#define T_TOK 8192
#define D_DIM 7168
#define E_EXP 256
#define N_GROUPS 8
#define EXP_PER_GROUP 32
#define TOPK_GROUPS 4
#define TOP_K 8

// GEMM tiling
#define BM 128
#define BN 64
#define BK 16
#define TM 8
#define TN 4
// threads: 16x16 = 256

// Scratch: sigmoid scores [T, E]  (8.4 MB) — static device array (no allocs allowed)
__device__ float g_scores[(size_t)T_TOK * E_EXP];

// ---------------------------------------------------------------------------
// Kernel 1: fp32 tiled GEMM  S = sigmoid(X @ W)
// grid: (E/BN, T/BM) = (4, 64), block: 256
// ---------------------------------------------------------------------------
__global__ __launch_bounds__(256, 3)
void gemm_sigmoid_kernel(const float* __restrict__ X,
                         const float* __restrict__ W)
{
    const int bc = blockIdx.x;          // N tile
    const int br = blockIdx.y;          // M tile
    const int tid = threadIdx.x;
    const int tx = tid & 15;            // 0..15  (N direction)
    const int ty = tid >> 4;            // 0..15  (M direction)

    __shared__ float As[BK][BM + 4];    // stride 132 floats (16B-aligned, conflict-light)
    __shared__ float Bs[BK][BN];

    const int m_base = br * BM;
    const int n_base = bc * BN;

    float acc[TM][TN];
#pragma unroll
    for (int i = 0; i < TM; i++)
#pragma unroll
        for (int j = 0; j < TN; j++) acc[i][j] = 0.0f;

    for (int k0 = 0; k0 < D_DIM; k0 += BK) {
        // --- load A tile (BM x BK) transposed into As[k][m]: 512 float4, 2/thread
#pragma unroll
        for (int i = 0; i < 2; i++) {
            int idx = tid + i * 256;
            int m   = idx >> 2;          // 0..127
            int k4  = (idx & 3) << 2;    // 0,4,8,12
            float4 v = *(const float4*)(X + (long)(m_base + m) * D_DIM + k0 + k4);
            As[k4 + 0][m] = v.x;
            As[k4 + 1][m] = v.y;
            As[k4 + 2][m] = v.z;
            As[k4 + 3][m] = v.w;
        }
        // --- load B tile (BK x BN): 256 float4, 1/thread
        {
            int k  = tid >> 4;           // 0..15
            int e4 = (tid & 15) << 2;    // 0..60
            float4 v = *(const float4*)(W + (long)(k0 + k) * E_EXP + n_base + e4);
            *(float4*)&Bs[k][e4] = v;
        }
        __syncthreads();

#pragma unroll
        for (int k = 0; k < BK; k++) {
            float a[TM], b[TN];
            float4 a0 = *(const float4*)&As[k][ty * TM];
            float4 a1 = *(const float4*)&As[k][ty * TM + 4];
            a[0]=a0.x; a[1]=a0.y; a[2]=a0.z; a[3]=a0.w;
            a[4]=a1.x; a[5]=a1.y; a[6]=a1.z; a[7]=a1.w;
            float4 b0 = *(const float4*)&Bs[k][tx * TN];
            b[0]=b0.x; b[1]=b0.y; b[2]=b0.z; b[3]=b0.w;
#pragma unroll
            for (int i = 0; i < TM; i++)
#pragma unroll
                for (int j = 0; j < TN; j++)
                    acc[i][j] = fmaf(a[i], b[j], acc[i][j]);
        }
        __syncthreads();
    }

    // epilogue: sigmoid, store to scratch
#pragma unroll
    for (int i = 0; i < TM; i++) {
        int m = m_base + ty * TM + i;
#pragma unroll
        for (int j = 0; j < TN; j++) {
            int n = n_base + tx * TN + j;
            float v = acc[i][j];
            float s = 1.0f / (1.0f + expf(-v));
            g_scores[(long)m * E_EXP + n] = s;
        }
    }
}

// ---------------------------------------------------------------------------
// Kernel 2: router. One block (256 threads) per token.
// warp w == group w (32 experts/lane each).
// ---------------------------------------------------------------------------
__global__ __launch_bounds__(256)
void router_kernel(const float* __restrict__ bias,
                   float* __restrict__ out,   // weights at [0, T*8)
                   int write_indices)         // indices (as float) at [T*8, 2*T*8)
{
    const int t    = blockIdx.x;
    const int tid  = threadIdx.x;
    const int lane = tid & 31;
    const int wid  = tid >> 5;      // group id

    __shared__ float score_sh[E_EXP];   // sigmoid scores (unbiased)
    __shared__ float s_sh[E_EXP];       // masked biased scores
    __shared__ float gscore[N_GROUPS];
    __shared__ int   gsel[N_GROUPS];

    const float sc = g_scores[(long)t * E_EXP + tid];
    const float s  = sc + bias[tid];
    score_sh[tid] = sc;

    // ---- group score: top-2 of s within each warp/group ----
    float v1 = s; int i1 = lane;
#pragma unroll
    for (int o = 16; o; o >>= 1) {
        float ov = __shfl_xor_sync(0xffffffffu, v1, o);
        int   oi = __shfl_xor_sync(0xffffffffu, i1, o);
        if (ov > v1 || (ov == v1 && oi < i1)) { v1 = ov; i1 = oi; }
    }
    float v2 = (lane == i1) ? -FLT_MAX : s;
#pragma unroll
    for (int o = 16; o; o >>= 1) {
        float ov = __shfl_xor_sync(0xffffffffu, v2, o);
        if (ov > v2) v2 = ov;
    }
    if (lane == 0) gscore[wid] = v1 + v2;
    if (tid < N_GROUPS) gsel[tid] = 0;
    __syncthreads();

    // ---- pick top-4 groups (serial, tie -> lower index) ----
    if (tid == 0) {
        float g[N_GROUPS];
#pragma unroll
        for (int i = 0; i < N_GROUPS; i++) g[i] = gscore[i];
#pragma unroll
        for (int r = 0; r < TOPK_GROUPS; r++) {
            int best = 0; float bv = g[0];
#pragma unroll
            for (int i = 1; i < N_GROUPS; i++)
                if (g[i] > bv) { bv = g[i]; best = i; }
            gsel[best] = 1;
            g[best] = -FLT_MAX;
        }
    }
    __syncthreads();

    // ---- masked biased scores ----
    s_sh[tid] = gsel[wid] ? s : 0.0f;
    __syncthreads();

    // ---- warp 0: top-8 over 256 masked values ----
    if (wid == 0) {
        float vals[8]; int idxs[8];
#pragma unroll
        for (int r = 0; r < 8; r++) {
            idxs[r] = r * 32 + lane;
            vals[r] = s_sh[idxs[r]];
        }
        int top[TOP_K];
#pragma unroll
        for (int r = 0; r < TOP_K; r++) {
            // local argmax over the 8 register slots (tie -> lower global idx)
            float bv = vals[0]; int bi = idxs[0]; int bslot = 0;
#pragma unroll
            for (int q = 1; q < 8; q++)
                if (vals[q] > bv || (vals[q] == bv && idxs[q] < bi)) {
                    bv = vals[q]; bi = idxs[q]; bslot = q;
                }
            // warp argmax
            float wv = bv; int wi = bi;
#pragma unroll
            for (int o = 16; o; o >>= 1) {
                float ov = __shfl_xor_sync(0xffffffffu, wv, o);
                int   oi = __shfl_xor_sync(0xffffffffu, wi, o);
                if (ov > wv || (ov == wv && oi < wi)) { wv = ov; wi = oi; }
            }
            if (bi == wi) vals[bslot] = -FLT_MAX;  // owner lane retires it
            top[r] = wi;
        }

        // ---- weights: unbiased sigmoid at top indices, normalized, x2.5 ----
        float w = 0.0f; int myidx = 0;
        if (lane < TOP_K) { myidx = top[lane]; w = score_sh[myidx]; }
        float sum = w;
#pragma unroll
        for (int o = 16; o; o >>= 1) sum += __shfl_xor_sync(0xffffffffu, sum, o);
        float weight = w / (sum + 1e-20f) * 2.5f;

        if (lane < TOP_K) {
            out[(long)t * TOP_K + lane] = weight;
            if (write_indices)
                out[(long)T_TOK * TOP_K + (long)t * TOP_K + lane] = (float)myidx;
        }
    }
}

// ---------------------------------------------------------------------------
extern "C" void kernel_launch(void* const* d_in, const int* in_sizes, int n_in,
                              void* d_out, int out_size)
{
    const float* X    = (const float*)d_in[0];   // [T, D]
    const float* W    = (const float*)d_in[1];   // [D, E]
    const float* bias = (const float*)d_in[2];   // [E]
    float* out = (float*)d_out;

    dim3 ggrid(E_EXP / BN, T_TOK / BM);
    gemm_sigmoid_kernel<<<ggrid, 256>>>(X, W);

    int write_indices = (out_size >= 2 * T_TOK * TOP_K) ? 1 : 0;
    router_kernel<<<T_TOK, 256>>>(bias, out, write_indices);
}